// round 5
// baseline (speedup 1.0000x reference)
#include <cuda_runtime.h>
#include <cstdint>
#include <cstddef>

#define T_STEPS 10
#define NB 8

// ---------------- scratch (device globals; no allocation) ----------------
__device__ uint32_t g_spk1[T_STEPS*NB*128*160];      // 32ch masks
__device__ uint32_t g_spk2[T_STEPS*NB*64*80*2];      // 64ch masks
__device__ uint32_t g_spk3[T_STEPS*NB*32*40*2];      // 64ch masks
__device__ uint32_t g_spk4[T_STEPS*NB*16*20*4];      // 128ch masks
__device__ float    g_S[10240*NB];                   // spike counts [k][b]
__device__ float    g_spk1f[NB*4096];                // fc1 spikes

__device__ __forceinline__ float lo32(unsigned long long v){ return __uint_as_float((uint32_t)v); }
__device__ __forceinline__ float hi32(unsigned long long v){ return __uint_as_float((uint32_t)(v>>32)); }

// ---------------- layer 1: conv 2->32 @256x320 + LIF + pool ----------------
__global__ void __launch_bounds__(256) k_l1(const float* __restrict__ x,
                                            const float* __restrict__ w1,
                                            const float* __restrict__ b1) {
    int id  = blockIdx.x*256 + threadIdx.x;
    int pos = id & 3, dh = pos >> 1, dw = pos & 1;
    int g   = (id >> 2) & 3;
    int rid = id >> 4;
    int wp  = rid % 160; rid /= 160;
    int hp  = rid % 128;
    int b   = rid / 128;

    float w0[8], w1r[8], bb[8], m[8];
    #pragma unroll
    for (int oo=0; oo<8; oo++) {
        int o = g*8+oo;
        w0[oo] = w1[2*o]; w1r[oo] = w1[2*o+1]; bb[oo] = b1[o];
        m[oo]  = 0.0f;
    }

    const float* xb0 = x + ((size_t)b)*163840 + (2*hp+dh)*320 + (2*wp+dw);
    #pragma unroll 1
    for (int t=0; t<T_STEPS; t++) {
        const float* xb = xb0 + (size_t)t*NB*163840;
        float x0 = xb[0];
        float x1 = xb[81920];
        uint32_t sb = 0;
        #pragma unroll
        for (int oo=0; oo<8; oo++) {
            float cur = fmaf(w1r[oo], x1, w0[oo]*x0) + bb[oo];
            float mo  = m[oo];
            float mn  = fmaf(0.95f, mo, cur) - ((mo>1.0f)?1.0f:0.0f);
            m[oo] = mn;
            sb |= ((mn>1.0f)?1u:0u) << oo;
        }
        sb <<= (g*8);
        sb |= __shfl_xor_sync(0xffffffffu, sb, 1);
        sb |= __shfl_xor_sync(0xffffffffu, sb, 2);
        sb |= __shfl_xor_sync(0xffffffffu, sb, 4);
        sb |= __shfl_xor_sync(0xffffffffu, sb, 8);
        if ((id & 15) == 0)
            g_spk1[((size_t)(t*NB+b)*128 + hp)*160 + wp] = sb;
    }
}

// ---- self-contained per-channel asm steps: bit test + LDS(imm) + predicated f32x2 adds ----
// OG=8: weights row = 32 bytes at [sbw + c*32]; accumulators a0..a3 hold ch pairs (0,1)..(6,7)
#define ST8(M,O1,O2) asm volatile("{\n\t" \
 ".reg .pred p;\n\t.reg .b32 t;\n\t.reg .b64 wa,wb,wc,wd;\n\t" \
 "and.b32 t, %4, " M ";\n\t" \
 "setp.ne.u32 p, t, 0;\n\t" \
 "ld.shared.v2.u64 {wa,wb}, [%5+" O1 "];\n\t" \
 "ld.shared.v2.u64 {wc,wd}, [%5+" O2 "];\n\t" \
 "@p add.rn.f32x2 %0, %0, wa;\n\t" \
 "@p add.rn.f32x2 %1, %1, wb;\n\t" \
 "@p add.rn.f32x2 %2, %2, wc;\n\t" \
 "@p add.rn.f32x2 %3, %3, wd;\n\t}" \
 : "+l"(a0), "+l"(a1), "+l"(a2), "+l"(a3) : "r"(mwreg), "r"(sbw))

#define WORD8() \
 ST8("0x00000001","0","16");    ST8("0x00000002","32","48");   \
 ST8("0x00000004","64","80");   ST8("0x00000008","96","112");  \
 ST8("0x00000010","128","144"); ST8("0x00000020","160","176"); \
 ST8("0x00000040","192","208"); ST8("0x00000080","224","240"); \
 ST8("0x00000100","256","272"); ST8("0x00000200","288","304"); \
 ST8("0x00000400","320","336"); ST8("0x00000800","352","368"); \
 ST8("0x00001000","384","400"); ST8("0x00002000","416","432"); \
 ST8("0x00004000","448","464"); ST8("0x00008000","480","496"); \
 ST8("0x00010000","512","528"); ST8("0x00020000","544","560"); \
 ST8("0x00040000","576","592"); ST8("0x00080000","608","624"); \
 ST8("0x00100000","640","656"); ST8("0x00200000","672","688"); \
 ST8("0x00400000","704","720"); ST8("0x00800000","736","752"); \
 ST8("0x01000000","768","784"); ST8("0x02000000","800","816"); \
 ST8("0x04000000","832","848"); ST8("0x08000000","864","880"); \
 ST8("0x10000000","896","912"); ST8("0x20000000","928","944"); \
 ST8("0x40000000","960","976"); ST8("0x80000000","992","1008");

// OG=4: weights row = 16 bytes at [sbw + c*16]; a0,a1 hold ch pairs (0,1),(2,3)
#define ST4(M,O1) asm volatile("{\n\t" \
 ".reg .pred p;\n\t.reg .b32 t;\n\t.reg .b64 wa,wb;\n\t" \
 "and.b32 t, %2, " M ";\n\t" \
 "setp.ne.u32 p, t, 0;\n\t" \
 "ld.shared.v2.u64 {wa,wb}, [%3+" O1 "];\n\t" \
 "@p add.rn.f32x2 %0, %0, wa;\n\t" \
 "@p add.rn.f32x2 %1, %1, wb;\n\t}" \
 : "+l"(a0), "+l"(a1) : "r"(mwreg), "r"(sbw))

#define WORD4() \
 ST4("0x00000001","0");   ST4("0x00000002","16");  \
 ST4("0x00000004","32");  ST4("0x00000008","48");  \
 ST4("0x00000010","64");  ST4("0x00000020","80");  \
 ST4("0x00000040","96");  ST4("0x00000080","112"); \
 ST4("0x00000100","128"); ST4("0x00000200","144"); \
 ST4("0x00000400","160"); ST4("0x00000800","176"); \
 ST4("0x00001000","192"); ST4("0x00002000","208"); \
 ST4("0x00004000","224"); ST4("0x00008000","240"); \
 ST4("0x00010000","256"); ST4("0x00020000","272"); \
 ST4("0x00040000","288"); ST4("0x00080000","304"); \
 ST4("0x00100000","320"); ST4("0x00200000","336"); \
 ST4("0x00400000","352"); ST4("0x00800000","368"); \
 ST4("0x01000000","384"); ST4("0x02000000","400"); \
 ST4("0x04000000","416"); ST4("0x08000000","432"); \
 ST4("0x10000000","448"); ST4("0x20000000","464"); \
 ST4("0x40000000","480"); ST4("0x80000000","496");

// ------------- conv(1x1 over bitmask spikes)+LIF+pool -------------
// Bit-exact vs flat fmaf(w, s, cur) chain over ascending channels.
template<int CIN, int COUT, int OG, int HIN, int WIN, int BS, bool COUNT>
__device__ __forceinline__ void conv_body(const uint32_t* __restrict__ in,
                                          uint8_t* __restrict__ outb,
                                          const float* __restrict__ wg,
                                          const float* __restrict__ bg) {
    constexpr int WRD = CIN/32;
    constexpr int HP  = HIN/2, WP = WIN/2;
    constexpr int NBY = COUT/8;

    __shared__ __align__(16) float wt[CIN*OG];      // wt[c][o] (transposed)
    const int ob = blockIdx.y * OG;
    for (int idx = threadIdx.x; idx < CIN*OG; idx += BS) {
        int c = idx / OG, o = idx % OG;
        wt[c*OG + o] = wg[(size_t)(ob+o)*CIN + c];
    }
    __syncthreads();

    uint32_t sbase;
    asm("{ .reg .u64 t0; cvta.to.shared.u64 t0, %1; cvt.u32.u64 %0, t0; }"
        : "=r"(sbase) : "l"(wt));

    int id  = blockIdx.x*BS + threadIdx.x;
    int pos = id & 3, dh = pos >> 1, dw = pos & 1;
    int rid = id >> 2;
    int wp  = rid % WP; rid /= WP;
    int hp  = rid % HP;
    int b   = rid / HP;

    float bb[OG], m[OG], cnt[OG];
    #pragma unroll
    for (int c=0; c<OG; c++) { bb[c] = bg[ob+c]; m[c] = 0.0f; cnt[c] = 0.0f; }

    const uint32_t* ibase = in + (((size_t)b*HIN + 2*hp+dh)*WIN + (2*wp+dw))*WRD;
    const size_t tstride  = (size_t)NB*HIN*WIN*WRD;

    #pragma unroll 1
    for (int t=0; t<T_STEPS; t++) {
        const uint32_t* ip = ibase + (size_t)t*tstride;
        uint32_t mw[WRD];
        if constexpr (WRD == 1) {
            mw[0] = ip[0];
        } else if constexpr (WRD == 2) {
            uint2 v = *(const uint2*)ip; mw[0]=v.x; mw[1]=v.y;
        } else {
            uint4 v = *(const uint4*)ip; mw[0]=v.x; mw[1]=v.y; mw[2]=v.z; mw[3]=v.w;
        }

        unsigned long long a0=0ULL, a1=0ULL, a2=0ULL, a3=0ULL;
        (void)a2; (void)a3;

        #pragma unroll
        for (int w=0; w<WRD; w++) {
            uint32_t mwreg = mw[w];
            uint32_t sbw   = sbase + w*(32*OG*4);
            if constexpr (OG == 8) { WORD8(); } else { WORD4(); }
        }

        float cur[OG];
        cur[0]=lo32(a0); cur[1]=hi32(a0); cur[2]=lo32(a1); cur[3]=hi32(a1);
        if constexpr (OG == 8) {
            cur[4]=lo32(a2); cur[5]=hi32(a2); cur[6]=lo32(a3); cur[7]=hi32(a3);
        }

        uint32_t sb = 0;
        #pragma unroll
        for (int c=0; c<OG; c++) {
            float cf = cur[c] + bb[c];
            float mo = m[c];
            float mn = fmaf(0.95f, mo, cf) - ((mo>1.0f)?1.0f:0.0f);
            m[c] = mn;
            sb |= ((mn>1.0f)?1u:0u) << c;
        }
        sb |= __shfl_xor_sync(0xffffffffu, sb, 1);
        sb |= __shfl_xor_sync(0xffffffffu, sb, 2);

        if constexpr (COUNT) {
            #pragma unroll
            for (int c=0; c<OG; c++) cnt[c] += (float)((sb>>c)&1u);
        } else {
            if (pos == 0)
                outb[(((size_t)(t*NB+b)*HP + hp)*WP + wp)*NBY + blockIdx.y] = (uint8_t)sb;
        }
    }

    if constexpr (COUNT) {
        if (pos == 0) {
            #pragma unroll
            for (int c=0; c<OG; c++)
                g_S[((size_t)(ob+c)*(HP*WP) + hp*WP + wp)*NB + b] = cnt[c];
        }
    }
}

__global__ void __launch_bounds__(256) k_l2(const float* __restrict__ wg, const float* __restrict__ bg){
    conv_body<32,64,8,128,160,256,false>(g_spk1, (uint8_t*)g_spk2, wg, bg);
}
__global__ void __launch_bounds__(256) k_l3(const float* __restrict__ wg, const float* __restrict__ bg){
    conv_body<64,64,8,64,80,256,false>(g_spk2, (uint8_t*)g_spk3, wg, bg);
}
__global__ void __launch_bounds__(128) k_l4(const float* __restrict__ wg, const float* __restrict__ bg){
    conv_body<64,128,8,32,40,128,false>(g_spk3, (uint8_t*)g_spk4, wg, bg);
}
__global__ void __launch_bounds__(128) k_l5(const float* __restrict__ wg, const float* __restrict__ bg){
    conv_body<128,128,4,16,20,128,true>(g_spk4, nullptr, wg, bg);
}

// ------------- fc1: [8,10240] @ [4096,10240]^T, spike -------------
__global__ void __launch_bounds__(128) k_fc1(const float* __restrict__ w,
                                             const float* __restrict__ bias) {
    __shared__ __align__(16) float sw[16*260];
    __shared__ __align__(16) float ss[8*260];
    int tid = threadIdx.x;
    int jl  = tid >> 3, b = tid & 7;
    int j   = blockIdx.x*16 + jl;

    float a0=0.f, a1=0.f, a2=0.f, a3=0.f;

    #pragma unroll 1
    for (int kt=0; kt<40; kt++) {
        __syncthreads();
        for (int i = tid; i < 1024; i += 128) {
            int r = i >> 6, c4 = i & 63;
            float4 v = *(const float4*)&w[(size_t)(blockIdx.x*16 + r)*10240 + kt*256 + c4*4];
            *(float4*)&sw[r*260 + c4*4] = v;
        }
        for (int i = tid; i < 2048; i += 128) {
            int k = i >> 3, bi = i & 7;
            ss[bi*260 + k] = g_S[(size_t)(kt*256 + k)*8 + bi];
        }
        __syncthreads();

        #pragma unroll 4
        for (int kk=0; kk<256; kk+=4) {
            float4 wv = *(const float4*)&sw[jl*260 + kk];
            float4 sv = *(const float4*)&ss[b*260 + kk];
            a0 = fmaf(wv.x, sv.x, a0);
            a1 = fmaf(wv.y, sv.y, a1);
            a2 = fmaf(wv.z, sv.z, a2);
            a3 = fmaf(wv.w, sv.w, a3);
        }
    }
    float mem = ((a0+a1)+(a2+a3)) + bias[j];
    g_spk1f[b*4096 + j] = (mem>1.0f) ? 1.0f : 0.0f;
}

// ------------- fc2: [8,4096] @ [4,4096]^T -> out[8,4] -------------
__global__ void __launch_bounds__(1024) k_fc2(const float* __restrict__ w,
                                              const float* __restrict__ bias,
                                              float* __restrict__ out) {
    int wid  = threadIdx.x >> 5;
    int lane = threadIdx.x & 31;
    int b = wid >> 2, i = wid & 3;
    float acc = 0.0f;
    for (int j = lane*4; j < 4096; j += 128) {
        float4 s  = *(const float4*)&g_spk1f[b*4096 + j];
        float4 wv = *(const float4*)&w[(size_t)i*4096 + j];
        acc = fmaf(wv.x, s.x, acc);
        acc = fmaf(wv.y, s.y, acc);
        acc = fmaf(wv.z, s.z, acc);
        acc = fmaf(wv.w, s.w, acc);
    }
    #pragma unroll
    for (int off=16; off; off>>=1) acc += __shfl_xor_sync(0xffffffffu, acc, off);
    if (lane == 0) out[b*4 + i] = acc + bias[i];
}

extern "C" void kernel_launch(void* const* d_in, const int* in_sizes, int n_in,
                              void* d_out, int out_size) {
    const float* x     = (const float*)d_in[0];
    const float* w1    = (const float*)d_in[1];
    const float* b1    = (const float*)d_in[2];
    const float* w2    = (const float*)d_in[3];
    const float* b2    = (const float*)d_in[4];
    const float* w3    = (const float*)d_in[5];
    const float* b3    = (const float*)d_in[6];
    const float* w4    = (const float*)d_in[7];
    const float* b4    = (const float*)d_in[8];
    const float* w5    = (const float*)d_in[9];
    const float* b5    = (const float*)d_in[10];
    const float* fc1_w = (const float*)d_in[11];
    const float* fc1_b = (const float*)d_in[12];
    const float* fc2_w = (const float*)d_in[13];
    const float* fc2_b = (const float*)d_in[14];

    k_l1<<<10240, 256>>>(x, w1, b1);
    { dim3 g(640, 8);  k_l2<<<g, 256>>>(w2, b2); }
    { dim3 g(160, 8);  k_l3<<<g, 256>>>(w3, b3); }
    { dim3 g(80, 16);  k_l4<<<g, 128>>>(w4, b4); }
    { dim3 g(20, 32);  k_l5<<<g, 128>>>(w5, b5); }
    k_fc1<<<256, 128>>>(fc1_w, fc1_b);
    k_fc2<<<1, 1024>>>(fc2_w, fc2_b, (float*)d_out);
}

// round 6
// speedup vs baseline: 1.1598x; 1.1598x over previous
#include <cuda_runtime.h>
#include <cstdint>
#include <cstddef>

#define T_STEPS 10
#define NB 8

// ---------------- scratch (device globals; no allocation) ----------------
__device__ uint32_t g_spk1[T_STEPS*NB*128*160];      // 32ch masks
__device__ uint32_t g_spk2[T_STEPS*NB*64*80*2];      // 64ch masks
__device__ uint32_t g_spk3[T_STEPS*NB*32*40*2];      // 64ch masks
__device__ uint32_t g_spk4[T_STEPS*NB*16*20*4];      // 128ch masks
__device__ float    g_S[10240*NB];                   // spike counts [k][b]
__device__ float    g_spk1f[NB*4096];                // fc1 spikes

__device__ __forceinline__ float lo32(unsigned long long v){ return __uint_as_float((uint32_t)v); }
__device__ __forceinline__ float hi32(unsigned long long v){ return __uint_as_float((uint32_t)(v>>32)); }

// ---------------- layer 1: conv 2->32 @256x320 + LIF + pool ----------------
__global__ void __launch_bounds__(256) k_l1(const float* __restrict__ x,
                                            const float* __restrict__ w1,
                                            const float* __restrict__ b1) {
    int id  = blockIdx.x*256 + threadIdx.x;
    int pos = id & 3, dh = pos >> 1, dw = pos & 1;
    int g   = (id >> 2) & 3;
    int rid = id >> 4;
    int wp  = rid % 160; rid /= 160;
    int hp  = rid % 128;
    int b   = rid / 128;

    float w0[8], w1r[8], bb[8], m[8];
    #pragma unroll
    for (int oo=0; oo<8; oo++) {
        int o = g*8+oo;
        w0[oo] = w1[2*o]; w1r[oo] = w1[2*o+1]; bb[oo] = b1[o];
        m[oo]  = 0.0f;
    }

    const float* xb0 = x + ((size_t)b)*163840 + (2*hp+dh)*320 + (2*wp+dw);
    #pragma unroll 1
    for (int t=0; t<T_STEPS; t++) {
        const float* xb = xb0 + (size_t)t*NB*163840;
        float x0 = xb[0];
        float x1 = xb[81920];
        uint32_t sb = 0;
        #pragma unroll
        for (int oo=0; oo<8; oo++) {
            float cur = fmaf(w1r[oo], x1, w0[oo]*x0) + bb[oo];
            float mo  = m[oo];
            float mn  = fmaf(0.95f, mo, cur) - ((mo>1.0f)?1.0f:0.0f);
            m[oo] = mn;
            sb |= ((mn>1.0f)?1u:0u) << oo;
        }
        sb <<= (g*8);
        sb |= __shfl_xor_sync(0xffffffffu, sb, 1);
        sb |= __shfl_xor_sync(0xffffffffu, sb, 2);
        sb |= __shfl_xor_sync(0xffffffffu, sb, 4);
        sb |= __shfl_xor_sync(0xffffffffu, sb, 8);
        if ((id & 15) == 0)
            g_spk1[((size_t)(t*NB+b)*128 + hp)*160 + wp] = sb;
    }
}

// ---- per-channel step: bit -> packed {s,s} float multiplier -> packed FFMA2 ----
// Bit-exact vs FADD chain: fma(w,1,acc)=rn(w+acc); fma(w,0,acc)=acc (mod ±0, harmless).
// OG=8: weights row = 32 bytes at [sbw + c*32]; acc pairs (0,1)..(6,7)
#define ST8(C,O1,O2) asm volatile("{\n\t" \
 ".reg .b32 t;\n\t.reg .b64 ss,wa,wb,wc,wd;\n\t" \
 "bfe.s32 t, %4, " C ", 1;\n\t" \
 "and.b32 t, t, 0x3f800000;\n\t" \
 "mov.b64 ss, {t, t};\n\t" \
 "ld.shared.v2.u64 {wa,wb}, [%5+" O1 "];\n\t" \
 "ld.shared.v2.u64 {wc,wd}, [%5+" O2 "];\n\t" \
 "fma.rn.f32x2 %0, wa, ss, %0;\n\t" \
 "fma.rn.f32x2 %1, wb, ss, %1;\n\t" \
 "fma.rn.f32x2 %2, wc, ss, %2;\n\t" \
 "fma.rn.f32x2 %3, wd, ss, %3;\n\t}" \
 : "+l"(a0), "+l"(a1), "+l"(a2), "+l"(a3) : "r"(mwreg), "r"(sbw))

#define WORD8() \
 ST8("0","0","16");     ST8("1","32","48");    \
 ST8("2","64","80");    ST8("3","96","112");   \
 ST8("4","128","144");  ST8("5","160","176");  \
 ST8("6","192","208");  ST8("7","224","240");  \
 ST8("8","256","272");  ST8("9","288","304");  \
 ST8("10","320","336"); ST8("11","352","368"); \
 ST8("12","384","400"); ST8("13","416","432"); \
 ST8("14","448","464"); ST8("15","480","496"); \
 ST8("16","512","528"); ST8("17","544","560"); \
 ST8("18","576","592"); ST8("19","608","624"); \
 ST8("20","640","656"); ST8("21","672","688"); \
 ST8("22","704","720"); ST8("23","736","752"); \
 ST8("24","768","784"); ST8("25","800","816"); \
 ST8("26","832","848"); ST8("27","864","880"); \
 ST8("28","896","912"); ST8("29","928","944"); \
 ST8("30","960","976"); ST8("31","992","1008");

// OG=4: weights row = 16 bytes at [sbw + c*16]; acc pairs (0,1),(2,3)
#define ST4(C,O1) asm volatile("{\n\t" \
 ".reg .b32 t;\n\t.reg .b64 ss,wa,wb;\n\t" \
 "bfe.s32 t, %2, " C ", 1;\n\t" \
 "and.b32 t, t, 0x3f800000;\n\t" \
 "mov.b64 ss, {t, t};\n\t" \
 "ld.shared.v2.u64 {wa,wb}, [%3+" O1 "];\n\t" \
 "fma.rn.f32x2 %0, wa, ss, %0;\n\t" \
 "fma.rn.f32x2 %1, wb, ss, %1;\n\t}" \
 : "+l"(a0), "+l"(a1) : "r"(mwreg), "r"(sbw))

#define WORD4() \
 ST4("0","0");    ST4("1","16");   ST4("2","32");   ST4("3","48");   \
 ST4("4","64");   ST4("5","80");   ST4("6","96");   ST4("7","112");  \
 ST4("8","128");  ST4("9","144");  ST4("10","160"); ST4("11","176"); \
 ST4("12","192"); ST4("13","208"); ST4("14","224"); ST4("15","240"); \
 ST4("16","256"); ST4("17","272"); ST4("18","288"); ST4("19","304"); \
 ST4("20","320"); ST4("21","336"); ST4("22","352"); ST4("23","368"); \
 ST4("24","384"); ST4("25","400"); ST4("26","416"); ST4("27","432"); \
 ST4("28","448"); ST4("29","464"); ST4("30","480"); ST4("31","496");

// ------------- conv(1x1 over bitmask spikes)+LIF+pool -------------
template<int CIN, int COUT, int OG, int HIN, int WIN, int BS, bool COUNT>
__device__ __forceinline__ void conv_body(const uint32_t* __restrict__ in,
                                          uint8_t* __restrict__ outb,
                                          const float* __restrict__ wg,
                                          const float* __restrict__ bg) {
    constexpr int WRD = CIN/32;
    constexpr int HP  = HIN/2, WP = WIN/2;
    constexpr int NBY = COUT/8;

    __shared__ __align__(16) float wt[CIN*OG];      // wt[c][o] (transposed)
    const int ob = blockIdx.y * OG;
    for (int idx = threadIdx.x; idx < CIN*OG; idx += BS) {
        int c = idx / OG, o = idx % OG;
        wt[c*OG + o] = wg[(size_t)(ob+o)*CIN + c];
    }
    __syncthreads();

    uint32_t sbase;
    asm("{ .reg .u64 t0; cvta.to.shared.u64 t0, %1; cvt.u32.u64 %0, t0; }"
        : "=r"(sbase) : "l"(wt));

    int id  = blockIdx.x*BS + threadIdx.x;
    int pos = id & 3, dh = pos >> 1, dw = pos & 1;
    int rid = id >> 2;
    int wp  = rid % WP; rid /= WP;
    int hp  = rid % HP;
    int b   = rid / HP;

    float bb[OG], m[OG], cnt[OG];
    #pragma unroll
    for (int c=0; c<OG; c++) { bb[c] = bg[ob+c]; m[c] = 0.0f; cnt[c] = 0.0f; }

    const uint32_t* ibase = in + (((size_t)b*HIN + 2*hp+dh)*WIN + (2*wp+dw))*WRD;
    const size_t tstride  = (size_t)NB*HIN*WIN*WRD;

    #pragma unroll 1
    for (int t=0; t<T_STEPS; t++) {
        const uint32_t* ip = ibase + (size_t)t*tstride;
        uint32_t mw[WRD];
        if constexpr (WRD == 1) {
            mw[0] = ip[0];
        } else if constexpr (WRD == 2) {
            uint2 v = *(const uint2*)ip; mw[0]=v.x; mw[1]=v.y;
        } else {
            uint4 v = *(const uint4*)ip; mw[0]=v.x; mw[1]=v.y; mw[2]=v.z; mw[3]=v.w;
        }

        unsigned long long a0=0ULL, a1=0ULL, a2=0ULL, a3=0ULL;
        (void)a2; (void)a3;

        #pragma unroll
        for (int w=0; w<WRD; w++) {
            uint32_t mwreg = mw[w];
            uint32_t sbw   = sbase + w*(32*OG*4);
            if constexpr (OG == 8) { WORD8(); } else { WORD4(); }
        }

        float cur[OG];
        cur[0]=lo32(a0); cur[1]=hi32(a0); cur[2]=lo32(a1); cur[3]=hi32(a1);
        if constexpr (OG == 8) {
            cur[4]=lo32(a2); cur[5]=hi32(a2); cur[6]=lo32(a3); cur[7]=hi32(a3);
        }

        uint32_t sb = 0;
        #pragma unroll
        for (int c=0; c<OG; c++) {
            float cf = cur[c] + bb[c];
            float mo = m[c];
            float mn = fmaf(0.95f, mo, cf) - ((mo>1.0f)?1.0f:0.0f);
            m[c] = mn;
            sb |= ((mn>1.0f)?1u:0u) << c;
        }
        sb |= __shfl_xor_sync(0xffffffffu, sb, 1);
        sb |= __shfl_xor_sync(0xffffffffu, sb, 2);

        if constexpr (COUNT) {
            #pragma unroll
            for (int c=0; c<OG; c++) cnt[c] += (float)((sb>>c)&1u);
        } else {
            if (pos == 0)
                outb[(((size_t)(t*NB+b)*HP + hp)*WP + wp)*NBY + blockIdx.y] = (uint8_t)sb;
        }
    }

    if constexpr (COUNT) {
        if (pos == 0) {
            #pragma unroll
            for (int c=0; c<OG; c++)
                g_S[((size_t)(ob+c)*(HP*WP) + hp*WP + wp)*NB + b] = cnt[c];
        }
    }
}

__global__ void __launch_bounds__(256) k_l2(const float* __restrict__ wg, const float* __restrict__ bg){
    conv_body<32,64,8,128,160,256,false>(g_spk1, (uint8_t*)g_spk2, wg, bg);
}
__global__ void __launch_bounds__(256) k_l3(const float* __restrict__ wg, const float* __restrict__ bg){
    conv_body<64,64,8,64,80,256,false>(g_spk2, (uint8_t*)g_spk3, wg, bg);
}
__global__ void __launch_bounds__(128) k_l4(const float* __restrict__ wg, const float* __restrict__ bg){
    conv_body<64,128,8,32,40,128,false>(g_spk3, (uint8_t*)g_spk4, wg, bg);
}
__global__ void __launch_bounds__(128) k_l5(const float* __restrict__ wg, const float* __restrict__ bg){
    conv_body<128,128,4,16,20,128,true>(g_spk4, nullptr, wg, bg);
}

// ------------- fc1: [8,10240] @ [4096,10240]^T, spike -------------
__global__ void __launch_bounds__(128) k_fc1(const float* __restrict__ w,
                                             const float* __restrict__ bias) {
    __shared__ __align__(16) float sw[16*260];
    __shared__ __align__(16) float ss[8*260];
    int tid = threadIdx.x;
    int jl  = tid >> 3, b = tid & 7;
    int j   = blockIdx.x*16 + jl;

    float a0=0.f, a1=0.f, a2=0.f, a3=0.f;

    #pragma unroll 1
    for (int kt=0; kt<40; kt++) {
        __syncthreads();
        for (int i = tid; i < 1024; i += 128) {
            int r = i >> 6, c4 = i & 63;
            float4 v = *(const float4*)&w[(size_t)(blockIdx.x*16 + r)*10240 + kt*256 + c4*4];
            *(float4*)&sw[r*260 + c4*4] = v;
        }
        for (int i = tid; i < 2048; i += 128) {
            int k = i >> 3, bi = i & 7;
            ss[bi*260 + k] = g_S[(size_t)(kt*256 + k)*8 + bi];
        }
        __syncthreads();

        #pragma unroll 4
        for (int kk=0; kk<256; kk+=4) {
            float4 wv = *(const float4*)&sw[jl*260 + kk];
            float4 sv = *(const float4*)&ss[b*260 + kk];
            a0 = fmaf(wv.x, sv.x, a0);
            a1 = fmaf(wv.y, sv.y, a1);
            a2 = fmaf(wv.z, sv.z, a2);
            a3 = fmaf(wv.w, sv.w, a3);
        }
    }
    float mem = ((a0+a1)+(a2+a3)) + bias[j];
    g_spk1f[b*4096 + j] = (mem>1.0f) ? 1.0f : 0.0f;
}

// ------------- fc2: [8,4096] @ [4,4096]^T -> out[8,4] -------------
__global__ void __launch_bounds__(1024) k_fc2(const float* __restrict__ w,
                                              const float* __restrict__ bias,
                                              float* __restrict__ out) {
    int wid  = threadIdx.x >> 5;
    int lane = threadIdx.x & 31;
    int b = wid >> 2, i = wid & 3;
    float acc = 0.0f;
    for (int j = lane*4; j < 4096; j += 128) {
        float4 s  = *(const float4*)&g_spk1f[b*4096 + j];
        float4 wv = *(const float4*)&w[(size_t)i*4096 + j];
        acc = fmaf(wv.x, s.x, acc);
        acc = fmaf(wv.y, s.y, acc);
        acc = fmaf(wv.z, s.z, acc);
        acc = fmaf(wv.w, s.w, acc);
    }
    #pragma unroll
    for (int off=16; off; off>>=1) acc += __shfl_xor_sync(0xffffffffu, acc, off);
    if (lane == 0) out[b*4 + i] = acc + bias[i];
}

extern "C" void kernel_launch(void* const* d_in, const int* in_sizes, int n_in,
                              void* d_out, int out_size) {
    const float* x     = (const float*)d_in[0];
    const float* w1    = (const float*)d_in[1];
    const float* b1    = (const float*)d_in[2];
    const float* w2    = (const float*)d_in[3];
    const float* b2    = (const float*)d_in[4];
    const float* w3    = (const float*)d_in[5];
    const float* b3    = (const float*)d_in[6];
    const float* w4    = (const float*)d_in[7];
    const float* b4    = (const float*)d_in[8];
    const float* w5    = (const float*)d_in[9];
    const float* b5    = (const float*)d_in[10];
    const float* fc1_w = (const float*)d_in[11];
    const float* fc1_b = (const float*)d_in[12];
    const float* fc2_w = (const float*)d_in[13];
    const float* fc2_b = (const float*)d_in[14];

    k_l1<<<10240, 256>>>(x, w1, b1);
    { dim3 g(640, 8);  k_l2<<<g, 256>>>(w2, b2); }
    { dim3 g(160, 8);  k_l3<<<g, 256>>>(w3, b3); }
    { dim3 g(80, 16);  k_l4<<<g, 128>>>(w4, b4); }
    { dim3 g(20, 32);  k_l5<<<g, 128>>>(w5, b5); }
    k_fc1<<<256, 128>>>(fc1_w, fc1_b);
    k_fc2<<<1, 1024>>>(fc2_w, fc2_b, (float*)d_out);
}